// round 5
// baseline (speedup 1.0000x reference)
#include <cuda_runtime.h>
#include <cstdint>

#define MDIM 8192
#define NDIM 4096
#define KDIM 4096

// ---------------- scratch (device globals; no allocation allowed) ----------------
__device__ __align__(16) uint8_t g_Xq[(size_t)MDIM * KDIM]; // 32 MB
__device__ __align__(16) int8_t  g_Wq[(size_t)NDIM * KDIM]; // 16 MB
__device__ float g_sa[MDIM];
__device__ int   g_zp[MDIM];
__device__ float g_sw[NDIM];
__device__ int   g_rws[NDIM];

// ---------------- weight quantization: row-wise symmetric int8 ----------------
__global__ void __launch_bounds__(128) quant_w_kernel(const float* __restrict__ w) {
    __shared__ float sm[4];
    __shared__ int   si[4];
    const int n = blockIdx.x, t = threadIdx.x;
    const float4* row = reinterpret_cast<const float4*>(w + (size_t)n * KDIM);
    float4 v[8];
    float am = 0.f;
#pragma unroll
    for (int i = 0; i < 8; i++) {
        v[i] = row[t + i * 128];
        am = fmaxf(am, fmaxf(fmaxf(fabsf(v[i].x), fabsf(v[i].y)),
                             fmaxf(fabsf(v[i].z), fabsf(v[i].w))));
    }
#pragma unroll
    for (int o = 16; o > 0; o >>= 1) am = fmaxf(am, __shfl_xor_sync(0xffffffffu, am, o));
    if ((t & 31) == 0) sm[t >> 5] = am;
    __syncthreads();
    am = fmaxf(fmaxf(sm[0], sm[1]), fmaxf(sm[2], sm[3]));
    const float scale = (am > 0.f) ? (am / 127.0f) : 1.0f;

    char4* out = reinterpret_cast<char4*>(g_Wq + (size_t)n * KDIM);
    int ssum = 0;
#pragma unroll
    for (int i = 0; i < 8; i++) {
        int qx = (int)fminf(fmaxf(rintf(v[i].x / scale), -127.f), 127.f);
        int qy = (int)fminf(fmaxf(rintf(v[i].y / scale), -127.f), 127.f);
        int qz = (int)fminf(fmaxf(rintf(v[i].z / scale), -127.f), 127.f);
        int qw = (int)fminf(fmaxf(rintf(v[i].w / scale), -127.f), 127.f);
        ssum += qx + qy + qz + qw;
        out[t + i * 128] = make_char4((char)qx, (char)qy, (char)qz, (char)qw);
    }
#pragma unroll
    for (int o = 16; o > 0; o >>= 1) ssum += __shfl_xor_sync(0xffffffffu, ssum, o);
    if ((t & 31) == 0) si[t >> 5] = ssum;
    __syncthreads();
    if (t == 0) {
        g_sw[n]  = scale;
        g_rws[n] = si[0] + si[1] + si[2] + si[3];
    }
}

// ---------------- activation quantization: per-token asymmetric uint8 ----------------
__global__ void __launch_bounds__(128) quant_x_kernel(const float* __restrict__ x) {
    __shared__ float smn[4], smx[4];
    const int m = blockIdx.x, t = threadIdx.x;
    const float4* row = reinterpret_cast<const float4*>(x + (size_t)m * KDIM);
    float4 v[8];
    float mn = 3.4e38f, mx = -3.4e38f;
#pragma unroll
    for (int i = 0; i < 8; i++) {
        v[i] = row[t + i * 128];
        mn = fminf(mn, fminf(fminf(v[i].x, v[i].y), fminf(v[i].z, v[i].w)));
        mx = fmaxf(mx, fmaxf(fmaxf(v[i].x, v[i].y), fmaxf(v[i].z, v[i].w)));
    }
#pragma unroll
    for (int o = 16; o > 0; o >>= 1) {
        mn = fminf(mn, __shfl_xor_sync(0xffffffffu, mn, o));
        mx = fmaxf(mx, __shfl_xor_sync(0xffffffffu, mx, o));
    }
    if ((t & 31) == 0) { smn[t >> 5] = mn; smx[t >> 5] = mx; }
    __syncthreads();
    mn = fminf(fminf(smn[0], smn[1]), fminf(smn[2], smn[3]));
    mx = fmaxf(fmaxf(smx[0], smx[1]), fmaxf(smx[2], smx[3]));
    const float rng   = mx - mn;
    const float scale = (rng > 0.f) ? (rng / 255.0f) : 1.0f;
    const float zpf   = rintf((-mn) / scale);

    uchar4* out = reinterpret_cast<uchar4*>(g_Xq + (size_t)m * KDIM);
#pragma unroll
    for (int i = 0; i < 8; i++) {
        float qx = fminf(fmaxf(rintf(v[i].x / scale) + zpf, 0.f), 255.f);
        float qy = fminf(fmaxf(rintf(v[i].y / scale) + zpf, 0.f), 255.f);
        float qz = fminf(fmaxf(rintf(v[i].z / scale) + zpf, 0.f), 255.f);
        float qw = fminf(fmaxf(rintf(v[i].w / scale) + zpf, 0.f), 255.f);
        out[t + i * 128] = make_uchar4((unsigned char)qx, (unsigned char)qy,
                                       (unsigned char)qz, (unsigned char)qw);
    }
    if (t == 0) { g_sa[m] = scale; g_zp[m] = (int)zpf; }
}

// ---------------- int8 GEMM: u8 x s8 -> s32, mma.sync m16n8k32 ----------------
#define BM 128
#define BN 128
#define BK 64

__device__ __forceinline__ unsigned swz(int row, int chunk) {
    // 64B rows, 16B chunks; phys chunk = c ^ ((row>>1)&3) -> conflict-free ldmatrix
    return (unsigned)(row * 64 + ((chunk ^ ((row >> 1) & 3)) << 4));
}

#define CP_ASYNC16(dst, src) \
    asm volatile("cp.async.cg.shared.global [%0], [%1], 16;\n" \
                 :: "r"(dst), "l"(__cvta_generic_to_global(src)))

#define LDSM_X4(R0, R1, R2, R3, A) \
    asm volatile("ldmatrix.sync.aligned.m8n8.x4.shared.b16 {%0,%1,%2,%3}, [%4];\n" \
                 : "=r"(R0), "=r"(R1), "=r"(R2), "=r"(R3) : "r"(A))

#define MMA_U8S8(C0, C1, C2, C3, A0, A1, A2, A3, B0, B1)               \
    asm volatile("mma.sync.aligned.m16n8k32.row.col.s32.u8.s8.s32 "    \
                 "{%0,%1,%2,%3}, {%4,%5,%6,%7}, {%8,%9}, {%0,%1,%2,%3};\n" \
                 : "+r"(C0), "+r"(C1), "+r"(C2), "+r"(C3)              \
                 : "r"(A0), "r"(A1), "r"(A2), "r"(A3), "r"(B0), "r"(B1))

__global__ void __launch_bounds__(256, 2) gemm_kernel(const float* __restrict__ bias,
                                                      float* __restrict__ out) {
    __shared__ __align__(128) uint8_t As[2][BM * BK];
    __shared__ __align__(128) uint8_t Bs[2][BN * BK];
    __shared__ float sSa[BM];
    __shared__ int   sZp[BM];
    __shared__ float sSw[BN];
    __shared__ int   sRw[BN];
    __shared__ float sBias[BN];

    const int t  = threadIdx.x;
    const int m0 = blockIdx.y * BM;
    const int n0 = blockIdx.x * BN;

    if (t < 128) {
        sSa[t] = g_sa[m0 + t];
        sZp[t] = g_zp[m0 + t];
    } else {
        const int c = t - 128;
        sSw[c]   = g_sw[n0 + c];
        sRw[c]   = g_rws[n0 + c];
        sBias[c] = bias[n0 + c];
    }

    const unsigned sA0 = (unsigned)__cvta_generic_to_shared(&As[0][0]);
    const unsigned sB0 = (unsigned)__cvta_generic_to_shared(&Bs[0][0]);

    // loader: 512 16B chunks per tile, 2 per thread (rows 0..63 and 64..127)
    const int c0row = t >> 2, cch = t & 3;
    const int c1row = c0row + 64;
    const uint8_t* gA0 = g_Xq + (size_t)(m0 + c0row) * KDIM + cch * 16;
    const uint8_t* gA1 = g_Xq + (size_t)(m0 + c1row) * KDIM + cch * 16;
    const uint8_t* gB0 = (const uint8_t*)g_Wq + (size_t)(n0 + c0row) * KDIM + cch * 16;
    const uint8_t* gB1 = (const uint8_t*)g_Wq + (size_t)(n0 + c1row) * KDIM + cch * 16;
    const unsigned swO0 = swz(c0row, cch), swO1 = swz(c1row, cch);

    // fragment addressing (ldmatrix row providers)
    const int warp = t >> 5, lane = t & 31;
    const int wm = warp >> 2;  // 0..1  (64 rows each)
    const int wn = warp & 3;   // 0..3  (32 cols each)
    const int aRow = wm * 64 + (lane & 7) + ((lane >> 3) & 1) * 8;
    const int aCh  = (lane >> 4) & 1;
    const int bRow = wn * 32 + (lane & 7) + ((lane >> 4) & 1) * 8;
    const int bCh  = (lane >> 3) & 1;

    int acc[4][4][4];
#pragma unroll
    for (int mi = 0; mi < 4; mi++)
#pragma unroll
        for (int ni = 0; ni < 4; ni++)
#pragma unroll
            for (int r = 0; r < 4; r++) acc[mi][ni][r] = 0;

    // prologue: load tile 0
    {
        CP_ASYNC16(sA0 + swO0, gA0);
        CP_ASYNC16(sA0 + swO1, gA1);
        CP_ASYNC16(sB0 + swO0, gB0);
        CP_ASYNC16(sB0 + swO1, gB1);
        asm volatile("cp.async.commit_group;\n");
    }

#pragma unroll 1
    for (int kt = 0; kt < KDIM / BK; kt++) {
        const int buf = kt & 1;
        if (kt + 1 < KDIM / BK) {
            const unsigned da = sA0 + (buf ^ 1) * (BM * BK);
            const unsigned db = sB0 + (buf ^ 1) * (BN * BK);
            const size_t ko = (size_t)(kt + 1) * BK;
            CP_ASYNC16(da + swO0, gA0 + ko);
            CP_ASYNC16(da + swO1, gA1 + ko);
            CP_ASYNC16(db + swO0, gB0 + ko);
            CP_ASYNC16(db + swO1, gB1 + ko);
            asm volatile("cp.async.commit_group;\n");
            asm volatile("cp.async.wait_group %0;\n" :: "n"(1));
        } else {
            asm volatile("cp.async.wait_group %0;\n" :: "n"(0));
        }
        __syncthreads();

        const unsigned sa = sA0 + buf * (BM * BK);
        const unsigned sb = sB0 + buf * (BN * BK);
#pragma unroll
        for (int ks = 0; ks < 2; ks++) {
            uint32_t a[4][4], b4[2][4];
#pragma unroll
            for (int mi = 0; mi < 4; mi++) {
                const unsigned ad = sa + swz(aRow + mi * 16, ks * 2 + aCh);
                LDSM_X4(a[mi][0], a[mi][1], a[mi][2], a[mi][3], ad);
            }
#pragma unroll
            for (int nj = 0; nj < 2; nj++) {
                const unsigned ad = sb + swz(bRow + nj * 16, ks * 2 + bCh);
                LDSM_X4(b4[nj][0], b4[nj][1], b4[nj][2], b4[nj][3], ad);
            }
#pragma unroll
            for (int mi = 0; mi < 4; mi++)
#pragma unroll
                for (int ni = 0; ni < 4; ni++) {
                    MMA_U8S8(acc[mi][ni][0], acc[mi][ni][1], acc[mi][ni][2], acc[mi][ni][3],
                             a[mi][0], a[mi][1], a[mi][2], a[mi][3],
                             b4[ni >> 1][(ni & 1) * 2], b4[ni >> 1][(ni & 1) * 2 + 1]);
                }
        }
        __syncthreads();
    }

    // epilogue: zero-point correction (exact int32) + dequant + bias
    const int rBase = wm * 64 + (lane >> 2);
    const int cBase = wn * 32 + (lane & 3) * 2;
#pragma unroll
    for (int mi = 0; mi < 4; mi++) {
        const int r0 = rBase + mi * 16;
        const int r1 = r0 + 8;
        const float sa0 = sSa[r0], sa1 = sSa[r1];
        const int   zp0 = sZp[r0], zp1 = sZp[r1];
        float* o0 = out + (size_t)(m0 + r0) * NDIM + n0;
        float* o1 = out + (size_t)(m0 + r1) * NDIM + n0;
#pragma unroll
        for (int ni = 0; ni < 4; ni++) {
            const int cc = cBase + ni * 8;
            const float sw0 = sSw[cc], sw1 = sSw[cc + 1];
            const int   rw0 = sRw[cc], rw1 = sRw[cc + 1];
            const float bb0 = sBias[cc], bb1 = sBias[cc + 1];
            float2 y0, y1;
            y0.x = (float)(acc[mi][ni][0] - zp0 * rw0) * (sa0 * sw0) + bb0;
            y0.y = (float)(acc[mi][ni][1] - zp0 * rw1) * (sa0 * sw1) + bb1;
            y1.x = (float)(acc[mi][ni][2] - zp1 * rw0) * (sa1 * sw0) + bb0;
            y1.y = (float)(acc[mi][ni][3] - zp1 * rw1) * (sa1 * sw1) + bb1;
            *reinterpret_cast<float2*>(o0 + cc) = y0;
            *reinterpret_cast<float2*>(o1 + cc) = y1;
        }
    }
}

// ---------------- launch ----------------
extern "C" void kernel_launch(void* const* d_in, const int* in_sizes, int n_in,
                              void* d_out, int out_size) {
    (void)in_sizes; (void)n_in; (void)out_size;
    const float* x    = (const float*)d_in[0];
    const float* w    = (const float*)d_in[1];
    const float* bias = (const float*)d_in[2];
    float* out = (float*)d_out;

    quant_w_kernel<<<NDIM, 128>>>(w);
    quant_x_kernel<<<MDIM, 128>>>(x);
    dim3 grid(NDIM / BN, MDIM / BM);
    gemm_kernel<<<grid, 256>>>(bias, out);
}